// round 4
// baseline (speedup 1.0000x reference)
#include <cuda_runtime.h>
#include <math.h>

// Problem constants (match reference setup_inputs)
#define DIMX 768
#define NST 16
#define NE 1536
#define NB 2
#define NL 2048
#define NBL (NB * NL)          // 4096 rows
#define TCH 64                 // chunk length for SSM scan
#define NCHUNK (NL / TCH)      // 32 chunks per sequence

typedef unsigned long long u64;

// -------- scratch (static __device__ — no allocation allowed) --------
__device__ float g_xn[(size_t)NBL * DIMX];     // rmsnorm output      12 MB
__device__ float g_xp[(size_t)NBL * NE];       // in-proj output      24 MB
__device__ float g_y[(size_t)NBL * NE];        // ssm output          24 MB
__device__ float g_sA[NST * NE];               // sigmoid(A), [n][e]
__device__ float g_sB[NST * NE];
__device__ float g_sC[NST * NE];
__device__ float g_cw[4 * NE];                 // conv weights, [k][e]
__device__ float g_hend[(size_t)NB * NCHUNK * NST * NE];  // 6 MB
__device__ float g_Hin[(size_t)NB * NCHUNK * NST * NE];   // 6 MB

__device__ __forceinline__ u64 fdup(float v) {
    unsigned int u = __float_as_uint(v);
    return ((u64)u << 32) | (u64)u;
}
__device__ __forceinline__ u64 ffma2(u64 a, u64 b, u64 c) {
    u64 d;
    asm("fma.rn.f32x2 %0, %1, %2, %3;" : "=l"(d) : "l"(a), "l"(b), "l"(c));
    return d;
}

// -------- precompute sigmoids + transposed layouts --------
__global__ void precompute_kernel(const float* __restrict__ A,
                                  const float* __restrict__ Bp,
                                  const float* __restrict__ C,
                                  const float* __restrict__ convw)
{
    int i = blockIdx.x * blockDim.x + threadIdx.x;
    if (i >= NST * NE) return;
    int n = i / NE, e = i % NE;
    g_sA[i] = 1.0f / (1.0f + expf(-A[e * NST + n]));
    g_sB[i] = 1.0f / (1.0f + expf(-Bp[e * NST + n]));
    g_sC[i] = 1.0f / (1.0f + expf(-C[e * NST + n]));
    if (n < 4) g_cw[n * NE + e] = convw[e * 4 + n];
}

// -------- RMSNorm --------
__global__ void rmsnorm_kernel(const float* __restrict__ x,
                               const float* __restrict__ gamma)
{
    int row = blockIdx.x;
    const float* xr = x + (size_t)row * DIMX;
    float s = 0.f;
    for (int j = threadIdx.x; j < DIMX; j += 256) {
        float v = xr[j];
        s = fmaf(v, v, s);
    }
    __shared__ float sh[8];
    #pragma unroll
    for (int o = 16; o; o >>= 1) s += __shfl_xor_sync(0xffffffffu, s, o);
    if ((threadIdx.x & 31) == 0) sh[threadIdx.x >> 5] = s;
    __syncthreads();
    if (threadIdx.x < 8) {
        float v = sh[threadIdx.x];
        #pragma unroll
        for (int o = 4; o; o >>= 1) v += __shfl_xor_sync(0xffu, v, o);
        if (threadIdx.x == 0) sh[0] = v;
    }
    __syncthreads();
    float rms = sqrtf(sh[0] * (1.0f / DIMX));
    float inv = 1.0f / (rms + 1e-6f);
    float* o = g_xn + (size_t)row * DIMX;
    for (int j = threadIdx.x; j < DIMX; j += 256)
        o[j] = gamma[j] * xr[j] * inv;
}

// -------- fp32x2 SIMT GEMM, double-buffered smem, K-tile = 16 --------
// C[M,N] = A[M,K] @ W[N,K]^T + bias (+ resid)
// Accumulators packed pairwise along M (f32x2). A pairs load natively from
// smem; W tile is stored duplicated (each value as {v,v} in a 64-bit word).
#define KT 16
template <bool RESID>
__global__ __launch_bounds__(256, 2)
void gemm_kernel(const float* __restrict__ A, const float* __restrict__ W,
                 const float* __restrict__ bias, const float* __restrict__ R,
                 float* __restrict__ Cout, int M, int N, int K)
{
    __shared__ float As[2][KT][128];    // 16 KB
    __shared__ u64   Ws2[2][KT][128];   // 32 KB (duplicated pairs)
    int tid = threadIdx.x;
    int m0 = blockIdx.y * 128, n0 = blockIdx.x * 128;
    int lr = tid >> 1, lc = (tid & 1) << 3;     // loader row / k-offset (0 or 8)
    const float* Ap = A + (size_t)(m0 + lr) * K + lc;
    const float* Wp = W + (size_t)(n0 + lr) * K + lc;
    int ty = tid >> 4, tx = tid & 15;

    u64 acc2[4][8];                      // rows {2i,2i+1} packed, 8 columns
    #pragma unroll
    for (int i = 0; i < 4; i++)
        #pragma unroll
        for (int j = 0; j < 8; j++) acc2[i][j] = 0ull;

    // prologue: load tile 0 into buffer 0
    float4 av0 = *(const float4*)(Ap);
    float4 av1 = *(const float4*)(Ap + 4);
    float4 wv0 = *(const float4*)(Wp);
    float4 wv1 = *(const float4*)(Wp + 4);
    As[0][lc + 0][lr] = av0.x; As[0][lc + 1][lr] = av0.y;
    As[0][lc + 2][lr] = av0.z; As[0][lc + 3][lr] = av0.w;
    As[0][lc + 4][lr] = av1.x; As[0][lc + 5][lr] = av1.y;
    As[0][lc + 6][lr] = av1.z; As[0][lc + 7][lr] = av1.w;
    Ws2[0][lc + 0][lr] = fdup(wv0.x); Ws2[0][lc + 1][lr] = fdup(wv0.y);
    Ws2[0][lc + 2][lr] = fdup(wv0.z); Ws2[0][lc + 3][lr] = fdup(wv0.w);
    Ws2[0][lc + 4][lr] = fdup(wv1.x); Ws2[0][lc + 5][lr] = fdup(wv1.y);
    Ws2[0][lc + 6][lr] = fdup(wv1.z); Ws2[0][lc + 7][lr] = fdup(wv1.w);
    __syncthreads();

    int buf = 0;
    for (int k0 = KT; k0 < K; k0 += KT) {
        // prefetch next tile (global -> regs) while computing current
        av0 = *(const float4*)(Ap + k0);
        av1 = *(const float4*)(Ap + k0 + 4);
        wv0 = *(const float4*)(Wp + k0);
        wv1 = *(const float4*)(Wp + k0 + 4);

        #pragma unroll
        for (int kk = 0; kk < KT; kk++) {
            const ulonglong2* ap = (const ulonglong2*)&As[buf][kk][ty * 8];
            ulonglong2 al = ap[0], ah = ap[1];
            u64 a2[4] = { al.x, al.y, ah.x, ah.y };
            const ulonglong2* bp = (const ulonglong2*)&Ws2[buf][kk][tx * 8];
            ulonglong2 b01 = bp[0], b23 = bp[1], b45 = bp[2], b67 = bp[3];
            u64 b2[8] = { b01.x, b01.y, b23.x, b23.y,
                          b45.x, b45.y, b67.x, b67.y };
            #pragma unroll
            for (int i = 0; i < 4; i++)
                #pragma unroll
                for (int j = 0; j < 8; j++)
                    acc2[i][j] = ffma2(a2[i], b2[j], acc2[i][j]);
        }

        int nb = buf ^ 1;
        As[nb][lc + 0][lr] = av0.x; As[nb][lc + 1][lr] = av0.y;
        As[nb][lc + 2][lr] = av0.z; As[nb][lc + 3][lr] = av0.w;
        As[nb][lc + 4][lr] = av1.x; As[nb][lc + 5][lr] = av1.y;
        As[nb][lc + 6][lr] = av1.z; As[nb][lc + 7][lr] = av1.w;
        Ws2[nb][lc + 0][lr] = fdup(wv0.x); Ws2[nb][lc + 1][lr] = fdup(wv0.y);
        Ws2[nb][lc + 2][lr] = fdup(wv0.z); Ws2[nb][lc + 3][lr] = fdup(wv0.w);
        Ws2[nb][lc + 4][lr] = fdup(wv1.x); Ws2[nb][lc + 5][lr] = fdup(wv1.y);
        Ws2[nb][lc + 6][lr] = fdup(wv1.z); Ws2[nb][lc + 7][lr] = fdup(wv1.w);
        __syncthreads();
        buf = nb;
    }

    // epilogue tile
    #pragma unroll
    for (int kk = 0; kk < KT; kk++) {
        const ulonglong2* ap = (const ulonglong2*)&As[buf][kk][ty * 8];
        ulonglong2 al = ap[0], ah = ap[1];
        u64 a2[4] = { al.x, al.y, ah.x, ah.y };
        const ulonglong2* bp = (const ulonglong2*)&Ws2[buf][kk][tx * 8];
        ulonglong2 b01 = bp[0], b23 = bp[1], b45 = bp[2], b67 = bp[3];
        u64 b2[8] = { b01.x, b01.y, b23.x, b23.y,
                      b45.x, b45.y, b67.x, b67.y };
        #pragma unroll
        for (int i = 0; i < 4; i++)
            #pragma unroll
            for (int j = 0; j < 8; j++)
                acc2[i][j] = ffma2(a2[i], b2[j], acc2[i][j]);
    }

    // unpack and store: acc2[i2][j] = { C[2*i2][j] (lo), C[2*i2+1][j] (hi) }
    #pragma unroll
    for (int i2 = 0; i2 < 4; i2++) {
        #pragma unroll
        for (int half = 0; half < 2; half++) {
            int m = m0 + ty * 8 + 2 * i2 + half;
            float cr[8];
            #pragma unroll
            for (int j = 0; j < 8; j++) {
                unsigned int u = half ? (unsigned int)(acc2[i2][j] >> 32)
                                      : (unsigned int)(acc2[i2][j] & 0xffffffffu);
                cr[j] = __uint_as_float(u);
            }
            #pragma unroll
            for (int j0 = 0; j0 < 8; j0 += 4) {
                int n = n0 + tx * 8 + j0;
                float4 v;
                v.x = cr[j0 + 0] + bias[n + 0];
                v.y = cr[j0 + 1] + bias[n + 1];
                v.z = cr[j0 + 2] + bias[n + 2];
                v.w = cr[j0 + 3] + bias[n + 3];
                if (RESID) {
                    const float4 r = *(const float4*)&R[(size_t)m * N + n];
                    v.x += r.x; v.y += r.y; v.z += r.z; v.w += r.w;
                }
                *(float4*)&Cout[(size_t)m * N + n] = v;
            }
        }
    }
}

// -------- SSM pass A: per-chunk local scan (zero init), store end states ----
__global__ __launch_bounds__(256) void ssm_passA_kernel()
{
    int gid = blockIdx.x * blockDim.x + threadIdx.x;
    if (gid >= NB * NCHUNK * NE) return;
    int e = gid % NE;
    int chunk = (gid / NE) % NCHUNK;
    int b = gid / (NE * NCHUNK);

    float a[NST], bc[NST];
    #pragma unroll
    for (int n = 0; n < NST; n++) {
        a[n] = g_sA[n * NE + e];
        bc[n] = g_sB[n * NE + e];
    }
    float w0 = g_cw[0 * NE + e], w1 = g_cw[1 * NE + e];
    float w2 = g_cw[2 * NE + e], w3 = g_cw[3 * NE + e];

    const float* xp = g_xp + (size_t)b * NL * NE + e;
    int t0 = chunk * TCH;
    float x3 = (t0 >= 3) ? xp[(size_t)(t0 - 3) * NE] : 0.f;
    float x2 = (t0 >= 2) ? xp[(size_t)(t0 - 2) * NE] : 0.f;
    float x1 = (t0 >= 1) ? xp[(size_t)(t0 - 1) * NE] : 0.f;

    float h[NST];
    #pragma unroll
    for (int n = 0; n < NST; n++) h[n] = 0.f;

    for (int t = t0; t < t0 + TCH; t++) {
        float xt = xp[(size_t)t * NE];
        float xc = fmaf(w0, x3, fmaf(w1, x2, fmaf(w2, x1, w3 * xt)));
        x3 = x2; x2 = x1; x1 = xt;
        #pragma unroll
        for (int n = 0; n < NST; n++)
            h[n] = fmaf(a[n], h[n], bc[n] * xc);
    }
    size_t base = ((size_t)(b * NCHUNK + chunk) * NST) * NE + e;
    #pragma unroll
    for (int n = 0; n < NST; n++) g_hend[base + (size_t)n * NE] = h[n];
}

// -------- SSM pass B: inter-chunk combine (length-NCHUNK sequential) --------
__global__ __launch_bounds__(256) void ssm_passB_kernel()
{
    int gid = blockIdx.x * blockDim.x + threadIdx.x;
    if (gid >= NB * NST * NE) return;
    int e = gid % NE;
    int n = (gid / NE) % NST;
    int b = gid / (NE * NST);

    float a = g_sA[n * NE + e];
    float aT = a;
    #pragma unroll
    for (int s = 0; s < 6; s++) aT *= aT;   // a^64 == a^TCH

    float H = 0.f;
    for (int c = 0; c < NCHUNK; c++) {
        size_t idx = ((size_t)(b * NCHUNK + c) * NST + n) * NE + e;
        g_Hin[idx] = H;
        H = fmaf(aT, H, g_hend[idx]);
    }
}

// -------- SSM pass C: replay each chunk with true incoming state, emit y ----
__global__ __launch_bounds__(256) void ssm_passC_kernel()
{
    int gid = blockIdx.x * blockDim.x + threadIdx.x;
    if (gid >= NB * NCHUNK * NE) return;
    int e = gid % NE;
    int chunk = (gid / NE) % NCHUNK;
    int b = gid / (NE * NCHUNK);

    float a[NST], bc[NST], cc[NST], h[NST];
    size_t base = ((size_t)(b * NCHUNK + chunk) * NST) * NE + e;
    #pragma unroll
    for (int n = 0; n < NST; n++) {
        a[n]  = g_sA[n * NE + e];
        bc[n] = g_sB[n * NE + e];
        cc[n] = g_sC[n * NE + e];
        h[n]  = g_Hin[base + (size_t)n * NE];
    }
    float w0 = g_cw[0 * NE + e], w1 = g_cw[1 * NE + e];
    float w2 = g_cw[2 * NE + e], w3 = g_cw[3 * NE + e];

    const float* xp = g_xp + (size_t)b * NL * NE + e;
    float* yo = g_y + (size_t)b * NL * NE + e;
    int t0 = chunk * TCH;
    float x3 = (t0 >= 3) ? xp[(size_t)(t0 - 3) * NE] : 0.f;
    float x2 = (t0 >= 2) ? xp[(size_t)(t0 - 2) * NE] : 0.f;
    float x1 = (t0 >= 1) ? xp[(size_t)(t0 - 1) * NE] : 0.f;

    for (int t = t0; t < t0 + TCH; t++) {
        float xt = xp[(size_t)t * NE];
        float xc = fmaf(w0, x3, fmaf(w1, x2, fmaf(w2, x1, w3 * xt)));
        x3 = x2; x2 = x1; x1 = xt;
        float p[NST];
        #pragma unroll
        for (int n = 0; n < NST; n++) {
            h[n] = fmaf(a[n], h[n], bc[n] * xc);
            p[n] = cc[n] * h[n];
        }
        // tree reduction to shorten the dependency chain
        #pragma unroll
        for (int st = 8; st >= 1; st >>= 1)
            #pragma unroll
            for (int n = 0; n < 8; n++)
                if (n < st) p[n] += p[n + st];
        yo[(size_t)t * NE] = p[0];
    }
}

// -------- launch --------
extern "C" void kernel_launch(void* const* d_in, const int* in_sizes, int n_in,
                              void* d_out, int out_size)
{
    const float* x      = (const float*)d_in[0];
    const float* gamma  = (const float*)d_in[1];
    const float* W_in   = (const float*)d_in[2];
    const float* b_in   = (const float*)d_in[3];
    const float* conv_w = (const float*)d_in[4];
    const float* A      = (const float*)d_in[5];
    const float* Bp     = (const float*)d_in[6];
    const float* C      = (const float*)d_in[7];
    const float* W_out  = (const float*)d_in[8];
    const float* b_out  = (const float*)d_in[9];
    float* out = (float*)d_out;

    void *p_xn, *p_xp, *p_y;
    cudaGetSymbolAddress(&p_xn, g_xn);
    cudaGetSymbolAddress(&p_xp, g_xp);
    cudaGetSymbolAddress(&p_y, g_y);

    precompute_kernel<<<(NST * NE + 255) / 256, 256>>>(A, Bp, C, conv_w);
    rmsnorm_kernel<<<NBL, 256>>>(x, gamma);

    dim3 g1(NE / 128, NBL / 128);
    gemm_kernel<false><<<g1, 256>>>((const float*)p_xn, W_in, b_in, nullptr,
                                    (float*)p_xp, NBL, NE, DIMX);

    int nA = NB * NCHUNK * NE;
    ssm_passA_kernel<<<(nA + 255) / 256, 256>>>();
    int nB_ = NB * NST * NE;
    ssm_passB_kernel<<<(nB_ + 255) / 256, 256>>>();
    ssm_passC_kernel<<<(nA + 255) / 256, 256>>>();

    dim3 g2(DIMX / 128, NBL / 128);
    gemm_kernel<true><<<g2, 256>>>((const float*)p_y, W_out, b_out, x,
                                   out, NBL, DIMX, NE);
}

// round 5
// speedup vs baseline: 2.4337x; 2.4337x over previous
#include <cuda_runtime.h>
#include <math.h>

// Problem constants (match reference setup_inputs)
#define DIMX 768
#define NST 16
#define NE 1536
#define NB 2
#define NL 2048
#define NBL (NB * NL)          // 4096 rows
#define TCH 32                 // chunk length for SSM scan
#define NCHUNK (NL / TCH)      // 64 chunks per sequence

// -------- scratch (static __device__ — no allocation allowed) --------
__device__ float g_xn[(size_t)NBL * DIMX];     // rmsnorm output      12 MB
__device__ float g_xp[(size_t)NBL * NE];       // in-proj output      24 MB
__device__ float g_y[(size_t)NBL * NE];        // ssm output          24 MB
__device__ float g_sA[NST * NE];               // sigmoid(A), [n][e]
__device__ float g_sB[NST * NE];
__device__ float g_sC[NST * NE];
__device__ float g_cw[4 * NE];                 // conv weights, [k][e]
__device__ float g_hend[(size_t)NB * NCHUNK * NST * NE];  // 12 MB
__device__ float g_Hin[(size_t)NB * NCHUNK * NST * NE];   // 12 MB

// -------- precompute sigmoids + transposed layouts --------
__global__ void precompute_kernel(const float* __restrict__ A,
                                  const float* __restrict__ Bp,
                                  const float* __restrict__ C,
                                  const float* __restrict__ convw)
{
    int i = blockIdx.x * blockDim.x + threadIdx.x;
    if (i >= NST * NE) return;
    int n = i / NE, e = i % NE;
    g_sA[i] = 1.0f / (1.0f + expf(-A[e * NST + n]));
    g_sB[i] = 1.0f / (1.0f + expf(-Bp[e * NST + n]));
    g_sC[i] = 1.0f / (1.0f + expf(-C[e * NST + n]));
    if (n < 4) g_cw[n * NE + e] = convw[e * 4 + n];
}

// -------- RMSNorm --------
__global__ void rmsnorm_kernel(const float* __restrict__ x,
                               const float* __restrict__ gamma)
{
    int row = blockIdx.x;
    const float* xr = x + (size_t)row * DIMX;
    float s = 0.f;
    for (int j = threadIdx.x; j < DIMX; j += 256) {
        float v = xr[j];
        s = fmaf(v, v, s);
    }
    __shared__ float sh[8];
    #pragma unroll
    for (int o = 16; o; o >>= 1) s += __shfl_xor_sync(0xffffffffu, s, o);
    if ((threadIdx.x & 31) == 0) sh[threadIdx.x >> 5] = s;
    __syncthreads();
    if (threadIdx.x < 8) {
        float v = sh[threadIdx.x];
        #pragma unroll
        for (int o = 4; o; o >>= 1) v += __shfl_xor_sync(0xffu, v, o);
        if (threadIdx.x == 0) sh[0] = v;
    }
    __syncthreads();
    float rms = sqrtf(sh[0] * (1.0f / DIMX));
    float inv = 1.0f / (rms + 1e-6f);
    float* o = g_xn + (size_t)row * DIMX;
    for (int j = threadIdx.x; j < DIMX; j += 256)
        o[j] = gamma[j] * xr[j] * inv;
}

// -------- fp32 SIMT GEMM, double-buffered smem, K-tile = 16 --------
// C[M,N] = A[M,K] @ W[N,K]^T + bias (+ resid)
#define KT 16
template <bool RESID>
__global__ __launch_bounds__(256)
void gemm_kernel(const float* __restrict__ A, const float* __restrict__ W,
                 const float* __restrict__ bias, const float* __restrict__ R,
                 float* __restrict__ Cout, int M, int N, int K)
{
    __shared__ float As[2][KT][128];
    __shared__ float Ws[2][KT][128];
    int tid = threadIdx.x;
    int m0 = blockIdx.y * 128, n0 = blockIdx.x * 128;
    int lr = tid >> 1, lc = (tid & 1) << 3;     // loader row / k-offset (0 or 8)
    const float* Ap = A + (size_t)(m0 + lr) * K + lc;
    const float* Wp = W + (size_t)(n0 + lr) * K + lc;
    int ty = tid >> 4, tx = tid & 15;

    float acc[8][8];
    #pragma unroll
    for (int i = 0; i < 8; i++)
        #pragma unroll
        for (int j = 0; j < 8; j++) acc[i][j] = 0.f;

    // prologue: load tile 0 into buffer 0
    float4 av0 = *(const float4*)(Ap);
    float4 av1 = *(const float4*)(Ap + 4);
    float4 wv0 = *(const float4*)(Wp);
    float4 wv1 = *(const float4*)(Wp + 4);
    As[0][lc + 0][lr] = av0.x; As[0][lc + 1][lr] = av0.y;
    As[0][lc + 2][lr] = av0.z; As[0][lc + 3][lr] = av0.w;
    As[0][lc + 4][lr] = av1.x; As[0][lc + 5][lr] = av1.y;
    As[0][lc + 6][lr] = av1.z; As[0][lc + 7][lr] = av1.w;
    Ws[0][lc + 0][lr] = wv0.x; Ws[0][lc + 1][lr] = wv0.y;
    Ws[0][lc + 2][lr] = wv0.z; Ws[0][lc + 3][lr] = wv0.w;
    Ws[0][lc + 4][lr] = wv1.x; Ws[0][lc + 5][lr] = wv1.y;
    Ws[0][lc + 6][lr] = wv1.z; Ws[0][lc + 7][lr] = wv1.w;
    __syncthreads();

    int buf = 0;
    for (int k0 = KT; k0 < K; k0 += KT) {
        // prefetch next tile (global -> regs) while computing current
        av0 = *(const float4*)(Ap + k0);
        av1 = *(const float4*)(Ap + k0 + 4);
        wv0 = *(const float4*)(Wp + k0);
        wv1 = *(const float4*)(Wp + k0 + 4);

        #pragma unroll
        for (int kk = 0; kk < KT; kk++) {
            float a[8], b[8];
            *(float4*)(a)     = *(const float4*)&As[buf][kk][ty * 8];
            *(float4*)(a + 4) = *(const float4*)&As[buf][kk][ty * 8 + 4];
            *(float4*)(b)     = *(const float4*)&Ws[buf][kk][tx * 8];
            *(float4*)(b + 4) = *(const float4*)&Ws[buf][kk][tx * 8 + 4];
            #pragma unroll
            for (int i = 0; i < 8; i++)
                #pragma unroll
                for (int j = 0; j < 8; j++)
                    acc[i][j] = fmaf(a[i], b[j], acc[i][j]);
        }

        int nb = buf ^ 1;
        As[nb][lc + 0][lr] = av0.x; As[nb][lc + 1][lr] = av0.y;
        As[nb][lc + 2][lr] = av0.z; As[nb][lc + 3][lr] = av0.w;
        As[nb][lc + 4][lr] = av1.x; As[nb][lc + 5][lr] = av1.y;
        As[nb][lc + 6][lr] = av1.z; As[nb][lc + 7][lr] = av1.w;
        Ws[nb][lc + 0][lr] = wv0.x; Ws[nb][lc + 1][lr] = wv0.y;
        Ws[nb][lc + 2][lr] = wv0.z; Ws[nb][lc + 3][lr] = wv0.w;
        Ws[nb][lc + 4][lr] = wv1.x; Ws[nb][lc + 5][lr] = wv1.y;
        Ws[nb][lc + 6][lr] = wv1.z; Ws[nb][lc + 7][lr] = wv1.w;
        __syncthreads();
        buf = nb;
    }

    // epilogue tile
    #pragma unroll
    for (int kk = 0; kk < KT; kk++) {
        float a[8], b[8];
        *(float4*)(a)     = *(const float4*)&As[buf][kk][ty * 8];
        *(float4*)(a + 4) = *(const float4*)&As[buf][kk][ty * 8 + 4];
        *(float4*)(b)     = *(const float4*)&Ws[buf][kk][tx * 8];
        *(float4*)(b + 4) = *(const float4*)&Ws[buf][kk][tx * 8 + 4];
        #pragma unroll
        for (int i = 0; i < 8; i++)
            #pragma unroll
            for (int j = 0; j < 8; j++)
                acc[i][j] = fmaf(a[i], b[j], acc[i][j]);
    }

    #pragma unroll
    for (int i = 0; i < 8; i++) {
        int m = m0 + ty * 8 + i;
        #pragma unroll
        for (int j0 = 0; j0 < 8; j0 += 4) {
            int n = n0 + tx * 8 + j0;
            float4 v;
            v.x = acc[i][j0 + 0] + bias[n + 0];
            v.y = acc[i][j0 + 1] + bias[n + 1];
            v.z = acc[i][j0 + 2] + bias[n + 2];
            v.w = acc[i][j0 + 3] + bias[n + 3];
            if (RESID) {
                const float4 r = *(const float4*)&R[(size_t)m * N + n];
                v.x += r.x; v.y += r.y; v.z += r.z; v.w += r.w;
            }
            *(float4*)&Cout[(size_t)m * N + n] = v;
        }
    }
}

// -------- SSM pass A: per-chunk local scan (zero init), store end states ----
__global__ __launch_bounds__(256) void ssm_passA_kernel()
{
    int gid = blockIdx.x * blockDim.x + threadIdx.x;
    if (gid >= NB * NCHUNK * NE) return;
    int e = gid % NE;
    int chunk = (gid / NE) % NCHUNK;
    int b = gid / (NE * NCHUNK);

    float a[NST], bc[NST];
    #pragma unroll
    for (int n = 0; n < NST; n++) {
        a[n] = g_sA[n * NE + e];
        bc[n] = g_sB[n * NE + e];
    }
    float w0 = g_cw[0 * NE + e], w1 = g_cw[1 * NE + e];
    float w2 = g_cw[2 * NE + e], w3 = g_cw[3 * NE + e];

    const float* xp = g_xp + (size_t)b * NL * NE + e;
    int t0 = chunk * TCH;
    float x3 = (t0 >= 3) ? xp[(size_t)(t0 - 3) * NE] : 0.f;
    float x2 = (t0 >= 2) ? xp[(size_t)(t0 - 2) * NE] : 0.f;
    float x1 = (t0 >= 1) ? xp[(size_t)(t0 - 1) * NE] : 0.f;

    float h[NST];
    #pragma unroll
    for (int n = 0; n < NST; n++) h[n] = 0.f;

    for (int t = t0; t < t0 + TCH; t++) {
        float xt = xp[(size_t)t * NE];
        float xc = fmaf(w0, x3, fmaf(w1, x2, fmaf(w2, x1, w3 * xt)));
        x3 = x2; x2 = x1; x1 = xt;
        #pragma unroll
        for (int n = 0; n < NST; n++)
            h[n] = fmaf(a[n], h[n], bc[n] * xc);
    }
    size_t base = ((size_t)(b * NCHUNK + chunk) * NST) * NE + e;
    #pragma unroll
    for (int n = 0; n < NST; n++) g_hend[base + (size_t)n * NE] = h[n];
}

// -------- SSM pass B: inter-chunk combine (length-NCHUNK sequential) --------
__global__ __launch_bounds__(256) void ssm_passB_kernel()
{
    int gid = blockIdx.x * blockDim.x + threadIdx.x;
    if (gid >= NB * NST * NE) return;
    int e = gid % NE;
    int n = (gid / NE) % NST;
    int b = gid / (NE * NST);

    float a = g_sA[n * NE + e];
    float aT = a;
    #pragma unroll
    for (int s = 0; s < 5; s++) aT *= aT;   // a^32 == a^TCH

    float H = 0.f;
    for (int c = 0; c < NCHUNK; c++) {
        size_t idx = ((size_t)(b * NCHUNK + c) * NST + n) * NE + e;
        g_Hin[idx] = H;
        H = fmaf(aT, H, g_hend[idx]);
    }
}

// -------- SSM pass C: replay each chunk with true incoming state, emit y ----
__global__ __launch_bounds__(256) void ssm_passC_kernel()
{
    int gid = blockIdx.x * blockDim.x + threadIdx.x;
    if (gid >= NB * NCHUNK * NE) return;
    int e = gid % NE;
    int chunk = (gid / NE) % NCHUNK;
    int b = gid / (NE * NCHUNK);

    float a[NST], bc[NST], cc[NST], h[NST];
    size_t base = ((size_t)(b * NCHUNK + chunk) * NST) * NE + e;
    #pragma unroll
    for (int n = 0; n < NST; n++) {
        a[n]  = g_sA[n * NE + e];
        bc[n] = g_sB[n * NE + e];
        cc[n] = g_sC[n * NE + e];
        h[n]  = g_Hin[base + (size_t)n * NE];
    }
    float w0 = g_cw[0 * NE + e], w1 = g_cw[1 * NE + e];
    float w2 = g_cw[2 * NE + e], w3 = g_cw[3 * NE + e];

    const float* xp = g_xp + (size_t)b * NL * NE + e;
    float* yo = g_y + (size_t)b * NL * NE + e;
    int t0 = chunk * TCH;
    float x3 = (t0 >= 3) ? xp[(size_t)(t0 - 3) * NE] : 0.f;
    float x2 = (t0 >= 2) ? xp[(size_t)(t0 - 2) * NE] : 0.f;
    float x1 = (t0 >= 1) ? xp[(size_t)(t0 - 1) * NE] : 0.f;

    for (int t = t0; t < t0 + TCH; t++) {
        float xt = xp[(size_t)t * NE];
        float xc = fmaf(w0, x3, fmaf(w1, x2, fmaf(w2, x1, w3 * xt)));
        x3 = x2; x2 = x1; x1 = xt;
        float p[NST];
        #pragma unroll
        for (int n = 0; n < NST; n++) {
            h[n] = fmaf(a[n], h[n], bc[n] * xc);
            p[n] = cc[n] * h[n];
        }
        // tree reduction to shorten the dependency chain
        #pragma unroll
        for (int st = 8; st >= 1; st >>= 1)
            #pragma unroll
            for (int n = 0; n < 8; n++)
                if (n < st) p[n] += p[n + st];
        yo[(size_t)t * NE] = p[0];
    }
}

// -------- launch --------
extern "C" void kernel_launch(void* const* d_in, const int* in_sizes, int n_in,
                              void* d_out, int out_size)
{
    const float* x      = (const float*)d_in[0];
    const float* gamma  = (const float*)d_in[1];
    const float* W_in   = (const float*)d_in[2];
    const float* b_in   = (const float*)d_in[3];
    const float* conv_w = (const float*)d_in[4];
    const float* A      = (const float*)d_in[5];
    const float* Bp     = (const float*)d_in[6];
    const float* C      = (const float*)d_in[7];
    const float* W_out  = (const float*)d_in[8];
    const float* b_out  = (const float*)d_in[9];
    float* out = (float*)d_out;

    void *p_xn, *p_xp, *p_y;
    cudaGetSymbolAddress(&p_xn, g_xn);
    cudaGetSymbolAddress(&p_xp, g_xp);
    cudaGetSymbolAddress(&p_y, g_y);

    precompute_kernel<<<(NST * NE + 255) / 256, 256>>>(A, Bp, C, conv_w);
    rmsnorm_kernel<<<NBL, 256>>>(x, gamma);

    dim3 g1(NE / 128, NBL / 128);
    gemm_kernel<false><<<g1, 256>>>((const float*)p_xn, W_in, b_in, nullptr,
                                    (float*)p_xp, NBL, NE, DIMX);

    int nA = NB * NCHUNK * NE;
    ssm_passA_kernel<<<(nA + 255) / 256, 256>>>();
    int nB_ = NB * NST * NE;
    ssm_passB_kernel<<<(nB_ + 255) / 256, 256>>>();
    ssm_passC_kernel<<<(nA + 255) / 256, 256>>>();

    dim3 g2(DIMX / 128, NBL / 128);
    gemm_kernel<true><<<g2, 256>>>((const float*)p_y, W_out, b_out, x,
                                   out, NBL, DIMX, NE);
}

// round 14
// speedup vs baseline: 5.1270x; 2.1067x over previous
#include <cuda_runtime.h>
#include <math.h>

// Problem constants (match reference setup_inputs)
#define DIMX 768
#define NST 16
#define NE 1536
#define NB 2
#define NL 2048
#define NBL (NB * NL)          // 4096 rows
#define TCH 32                 // chunk length for SSM scan
#define NCHUNK (NL / TCH)      // 64 chunks per sequence

// -------- scratch (static __device__ — no allocation allowed) --------
__device__ float g_xn[(size_t)NBL * DIMX];     // rmsnorm output
__device__ float g_xp[(size_t)NBL * NE];       // in-proj output
__device__ float g_y[(size_t)NBL * NE];        // ssm output
__device__ float g_sA[NST * NE];               // sigmoid(A), [n][e]
__device__ float g_sB[NST * NE];
__device__ float g_sC[NST * NE];
__device__ float g_cw[4 * NE];                 // conv weights, [k][e]
__device__ float g_hend[(size_t)NB * NCHUNK * NST * NE];
__device__ float g_Hin[(size_t)NB * NCHUNK * NST * NE];

__device__ __forceinline__ unsigned cvt_tf32(float f) {
    unsigned r;
    asm("cvt.rna.tf32.f32 %0, %1;" : "=r"(r) : "f"(f));
    return r;
}

__device__ __forceinline__ void mma_tf32(float* d, const unsigned* a, const unsigned* b) {
    asm("mma.sync.aligned.m16n8k8.row.col.f32.tf32.tf32.f32 "
        "{%0,%1,%2,%3}, {%4,%5,%6,%7}, {%8,%9}, {%0,%1,%2,%3};"
        : "+f"(d[0]), "+f"(d[1]), "+f"(d[2]), "+f"(d[3])
        : "r"(a[0]), "r"(a[1]), "r"(a[2]), "r"(a[3]),
          "r"(b[0]), "r"(b[1]));
}

// -------- precompute sigmoids + transposed layouts --------
__global__ void precompute_kernel(const float* __restrict__ A,
                                  const float* __restrict__ Bp,
                                  const float* __restrict__ C,
                                  const float* __restrict__ convw)
{
    int i = blockIdx.x * blockDim.x + threadIdx.x;
    if (i >= NST * NE) return;
    int n = i / NE, e = i % NE;
    g_sA[i] = 1.0f / (1.0f + expf(-A[e * NST + n]));
    g_sB[i] = 1.0f / (1.0f + expf(-Bp[e * NST + n]));
    g_sC[i] = 1.0f / (1.0f + expf(-C[e * NST + n]));
    if (n < 4) g_cw[n * NE + e] = convw[e * 4 + n];
}

// -------- RMSNorm --------
__global__ void rmsnorm_kernel(const float* __restrict__ x,
                               const float* __restrict__ gamma)
{
    int row = blockIdx.x;
    const float* xr = x + (size_t)row * DIMX;
    float s = 0.f;
    for (int j = threadIdx.x; j < DIMX; j += 256) {
        float v = xr[j];
        s = fmaf(v, v, s);
    }
    __shared__ float sh[8];
    #pragma unroll
    for (int o = 16; o; o >>= 1) s += __shfl_xor_sync(0xffffffffu, s, o);
    if ((threadIdx.x & 31) == 0) sh[threadIdx.x >> 5] = s;
    __syncthreads();
    if (threadIdx.x < 8) {
        float v = sh[threadIdx.x];
        #pragma unroll
        for (int o = 4; o; o >>= 1) v += __shfl_xor_sync(0xffu, v, o);
        if (threadIdx.x == 0) sh[0] = v;
    }
    __syncthreads();
    float rms = sqrtf(sh[0] * (1.0f / DIMX));
    float inv = 1.0f / (rms + 1e-6f);
    float* o = g_xn + (size_t)row * DIMX;
    for (int j = threadIdx.x; j < DIMX; j += 256)
        o[j] = gamma[j] * xr[j] * inv;
}

// -------- tf32 tensor-core GEMM (mma.sync m16n8k8), double-buffered --------
// C[M,N] = A[M,K] @ W[N,K]^T + bias (+ resid)
// CTA 128x128, 8 warps, warp tile 64x32 (4x4 fragments of 16x8).
#define KT 16
#define PAD 20
template <bool RESID>
__global__ __launch_bounds__(256)
void gemm_tc_kernel(const float* __restrict__ A, const float* __restrict__ W,
                    const float* __restrict__ bias, const float* __restrict__ R,
                    float* __restrict__ Cout, int M, int N, int K)
{
    __shared__ unsigned As[2][128][PAD];
    __shared__ unsigned Ws[2][128][PAD];
    int tid = threadIdx.x;
    int m0 = blockIdx.y * 128, n0 = blockIdx.x * 128;
    int lr = tid >> 1, lc = (tid & 1) << 3;     // loader row / k-offset (0 or 8)
    const float* Ap = A + (size_t)(m0 + lr) * K + lc;
    const float* Wp = W + (size_t)(n0 + lr) * K + lc;

    int warp = tid >> 5, lane = tid & 31;
    int wm = (warp & 1) * 64;        // warp m-offset within CTA tile
    int wn = (warp >> 1) * 32;       // warp n-offset
    int gid = lane >> 2, tig = lane & 3;

    float acc[4][4][4];              // [mi][ni][frag]
    #pragma unroll
    for (int mi = 0; mi < 4; mi++)
        #pragma unroll
        for (int ni = 0; ni < 4; ni++)
            #pragma unroll
            for (int f = 0; f < 4; f++) acc[mi][ni][f] = 0.f;

    // prologue: load tile 0
    {
        float4 av0 = *(const float4*)(Ap);
        float4 av1 = *(const float4*)(Ap + 4);
        float4 wv0 = *(const float4*)(Wp);
        float4 wv1 = *(const float4*)(Wp + 4);
        uint4 ac0 = { cvt_tf32(av0.x), cvt_tf32(av0.y), cvt_tf32(av0.z), cvt_tf32(av0.w) };
        uint4 ac1 = { cvt_tf32(av1.x), cvt_tf32(av1.y), cvt_tf32(av1.z), cvt_tf32(av1.w) };
        uint4 wc0 = { cvt_tf32(wv0.x), cvt_tf32(wv0.y), cvt_tf32(wv0.z), cvt_tf32(wv0.w) };
        uint4 wc1 = { cvt_tf32(wv1.x), cvt_tf32(wv1.y), cvt_tf32(wv1.z), cvt_tf32(wv1.w) };
        *(uint4*)&As[0][lr][lc]     = ac0;
        *(uint4*)&As[0][lr][lc + 4] = ac1;
        *(uint4*)&Ws[0][lr][lc]     = wc0;
        *(uint4*)&Ws[0][lr][lc + 4] = wc1;
    }
    __syncthreads();

    int buf = 0;
    for (int k0 = KT; k0 < K; k0 += KT) {
        // global prefetch overlapped with compute
        float4 av0 = *(const float4*)(Ap + k0);
        float4 av1 = *(const float4*)(Ap + k0 + 4);
        float4 wv0 = *(const float4*)(Wp + k0);
        float4 wv1 = *(const float4*)(Wp + k0 + 4);

        #pragma unroll
        for (int ks = 0; ks < KT; ks += 8) {
            unsigned af[4][4], bf[4][2];
            #pragma unroll
            for (int mi = 0; mi < 4; mi++) {
                int row = wm + mi * 16;
                af[mi][0] = As[buf][row + gid][ks + tig];
                af[mi][1] = As[buf][row + gid + 8][ks + tig];
                af[mi][2] = As[buf][row + gid][ks + tig + 4];
                af[mi][3] = As[buf][row + gid + 8][ks + tig + 4];
            }
            #pragma unroll
            for (int ni = 0; ni < 4; ni++) {
                int col = wn + ni * 8;
                bf[ni][0] = Ws[buf][col + gid][ks + tig];
                bf[ni][1] = Ws[buf][col + gid][ks + tig + 4];
            }
            #pragma unroll
            for (int mi = 0; mi < 4; mi++)
                #pragma unroll
                for (int ni = 0; ni < 4; ni++)
                    mma_tf32(acc[mi][ni], af[mi], bf[ni]);
        }

        int nb = buf ^ 1;
        uint4 ac0 = { cvt_tf32(av0.x), cvt_tf32(av0.y), cvt_tf32(av0.z), cvt_tf32(av0.w) };
        uint4 ac1 = { cvt_tf32(av1.x), cvt_tf32(av1.y), cvt_tf32(av1.z), cvt_tf32(av1.w) };
        uint4 wc0 = { cvt_tf32(wv0.x), cvt_tf32(wv0.y), cvt_tf32(wv0.z), cvt_tf32(wv0.w) };
        uint4 wc1 = { cvt_tf32(wv1.x), cvt_tf32(wv1.y), cvt_tf32(wv1.z), cvt_tf32(wv1.w) };
        *(uint4*)&As[nb][lr][lc]     = ac0;
        *(uint4*)&As[nb][lr][lc + 4] = ac1;
        *(uint4*)&Ws[nb][lr][lc]     = wc0;
        *(uint4*)&Ws[nb][lr][lc + 4] = wc1;
        __syncthreads();
        buf = nb;
    }

    // epilogue tile
    #pragma unroll
    for (int ks = 0; ks < KT; ks += 8) {
        unsigned af[4][4], bf[4][2];
        #pragma unroll
        for (int mi = 0; mi < 4; mi++) {
            int row = wm + mi * 16;
            af[mi][0] = As[buf][row + gid][ks + tig];
            af[mi][1] = As[buf][row + gid + 8][ks + tig];
            af[mi][2] = As[buf][row + gid][ks + tig + 4];
            af[mi][3] = As[buf][row + gid + 8][ks + tig + 4];
        }
        #pragma unroll
        for (int ni = 0; ni < 4; ni++) {
            int col = wn + ni * 8;
            bf[ni][0] = Ws[buf][col + gid][ks + tig];
            bf[ni][1] = Ws[buf][col + gid][ks + tig + 4];
        }
        #pragma unroll
        for (int mi = 0; mi < 4; mi++)
            #pragma unroll
            for (int ni = 0; ni < 4; ni++)
                mma_tf32(acc[mi][ni], af[mi], bf[ni]);
    }

    // store: frag (mi,ni): c0,c1 at (m, n), (m, n+1); c2,c3 at (m+8, n..n+1)
    #pragma unroll
    for (int mi = 0; mi < 4; mi++) {
        #pragma unroll
        for (int ni = 0; ni < 4; ni++) {
            int m = m0 + wm + mi * 16 + gid;
            int n = n0 + wn + ni * 8 + tig * 2;
            float2 v0, v1;
            v0.x = acc[mi][ni][0] + bias[n];
            v0.y = acc[mi][ni][1] + bias[n + 1];
            v1.x = acc[mi][ni][2] + bias[n];
            v1.y = acc[mi][ni][3] + bias[n + 1];
            if (RESID) {
                float2 r0 = *(const float2*)&R[(size_t)m * N + n];
                float2 r1 = *(const float2*)&R[(size_t)(m + 8) * N + n];
                v0.x += r0.x; v0.y += r0.y;
                v1.x += r1.x; v1.y += r1.y;
            }
            *(float2*)&Cout[(size_t)m * N + n] = v0;
            *(float2*)&Cout[(size_t)(m + 8) * N + n] = v1;
        }
    }
}

// -------- SSM pass A: per-chunk local scan, 4x-unrolled (MLP=4) ----------
__global__ __launch_bounds__(256) void ssm_passA_kernel()
{
    int gid = blockIdx.x * blockDim.x + threadIdx.x;
    if (gid >= NB * NCHUNK * NE) return;
    int e = gid % NE;
    int chunk = (gid / NE) % NCHUNK;
    int b = gid / (NE * NCHUNK);

    float a[NST], bc[NST];
    #pragma unroll
    for (int n = 0; n < NST; n++) {
        a[n] = g_sA[n * NE + e];
        bc[n] = g_sB[n * NE + e];
    }
    float w0 = g_cw[0 * NE + e], w1 = g_cw[1 * NE + e];
    float w2 = g_cw[2 * NE + e], w3 = g_cw[3 * NE + e];

    const float* xp = g_xp + (size_t)b * NL * NE + e;
    int t0 = chunk * TCH;
    float x3 = (t0 >= 3) ? xp[(size_t)(t0 - 3) * NE] : 0.f;
    float x2 = (t0 >= 2) ? xp[(size_t)(t0 - 2) * NE] : 0.f;
    float x1 = (t0 >= 1) ? xp[(size_t)(t0 - 1) * NE] : 0.f;

    float h[NST];
    #pragma unroll
    for (int n = 0; n < NST; n++) h[n] = 0.f;

    for (int t = t0; t < t0 + TCH; t += 4) {
        // batch 4 independent loads up front (MLP = 4)
        float xt0 = xp[(size_t)(t + 0) * NE];
        float xt1 = xp[(size_t)(t + 1) * NE];
        float xt2 = xp[(size_t)(t + 2) * NE];
        float xt3 = xp[(size_t)(t + 3) * NE];
        float c0 = fmaf(w0, x3,  fmaf(w1, x2,  fmaf(w2, x1,  w3 * xt0)));
        float c1 = fmaf(w0, x2,  fmaf(w1, x1,  fmaf(w2, xt0, w3 * xt1)));
        float c2 = fmaf(w0, x1,  fmaf(w1, xt0, fmaf(w2, xt1, w3 * xt2)));
        float c3 = fmaf(w0, xt0, fmaf(w1, xt1, fmaf(w2, xt2, w3 * xt3)));
        x3 = xt1; x2 = xt2; x1 = xt3;
        #pragma unroll
        for (int n = 0; n < NST; n++) {
            h[n] = fmaf(a[n], h[n], bc[n] * c0);
            h[n] = fmaf(a[n], h[n], bc[n] * c1);
            h[n] = fmaf(a[n], h[n], bc[n] * c2);
            h[n] = fmaf(a[n], h[n], bc[n] * c3);
        }
    }
    size_t base = ((size_t)(b * NCHUNK + chunk) * NST) * NE + e;
    #pragma unroll
    for (int n = 0; n < NST; n++) g_hend[base + (size_t)n * NE] = h[n];
}

// -------- SSM pass B: inter-chunk combine (length-NCHUNK sequential) --------
__global__ __launch_bounds__(256) void ssm_passB_kernel()
{
    int gid = blockIdx.x * blockDim.x + threadIdx.x;
    if (gid >= NB * NST * NE) return;
    int e = gid % NE;
    int n = (gid / NE) % NST;
    int b = gid / (NE * NST);

    float a = g_sA[n * NE + e];
    float aT = a;
    #pragma unroll
    for (int s = 0; s < 5; s++) aT *= aT;   // a^32 == a^TCH

    float H = 0.f;
    for (int c = 0; c < NCHUNK; c++) {
        size_t idx = ((size_t)(b * NCHUNK + c) * NST + n) * NE + e;
        g_Hin[idx] = H;
        H = fmaf(aT, H, g_hend[idx]);
    }
}

// -------- SSM pass C: replay with true incoming state, 4x-unrolled ---------
__global__ __launch_bounds__(256) void ssm_passC_kernel()
{
    int gid = blockIdx.x * blockDim.x + threadIdx.x;
    if (gid >= NB * NCHUNK * NE) return;
    int e = gid % NE;
    int chunk = (gid / NE) % NCHUNK;
    int b = gid / (NE * NCHUNK);

    float a[NST], bc[NST], cc[NST], h[NST];
    size_t base = ((size_t)(b * NCHUNK + chunk) * NST) * NE + e;
    #pragma unroll
    for (int n = 0; n < NST; n++) {
        a[n]  = g_sA[n * NE + e];
        bc[n] = g_sB[n * NE + e];
        cc[n] = g_sC[n * NE + e];
        h[n]  = g_Hin[base + (size_t)n * NE];
    }
    float w0 = g_cw[0 * NE + e], w1 = g_cw[1 * NE + e];
    float w2 = g_cw[2 * NE + e], w3 = g_cw[3 * NE + e];

    const float* xp = g_xp + (size_t)b * NL * NE + e;
    float* yo = g_y + (size_t)b * NL * NE + e;
    int t0 = chunk * TCH;
    float x3 = (t0 >= 3) ? xp[(size_t)(t0 - 3) * NE] : 0.f;
    float x2 = (t0 >= 2) ? xp[(size_t)(t0 - 2) * NE] : 0.f;
    float x1 = (t0 >= 1) ? xp[(size_t)(t0 - 1) * NE] : 0.f;

    for (int t = t0; t < t0 + TCH; t += 4) {
        float xt0 = xp[(size_t)(t + 0) * NE];
        float xt1 = xp[(size_t)(t + 1) * NE];
        float xt2 = xp[(size_t)(t + 2) * NE];
        float xt3 = xp[(size_t)(t + 3) * NE];
        float c[4];
        c[0] = fmaf(w0, x3,  fmaf(w1, x2,  fmaf(w2, x1,  w3 * xt0)));
        c[1] = fmaf(w0, x2,  fmaf(w1, x1,  fmaf(w2, xt0, w3 * xt1)));
        c[2] = fmaf(w0, x1,  fmaf(w1, xt0, fmaf(w2, xt1, w3 * xt2)));
        c[3] = fmaf(w0, xt0, fmaf(w1, xt1, fmaf(w2, xt2, w3 * xt3)));
        x3 = xt1; x2 = xt2; x1 = xt3;
        #pragma unroll
        for (int s = 0; s < 4; s++) {
            float p[NST];
            #pragma unroll
            for (int n = 0; n < NST; n++) {
                h[n] = fmaf(a[n], h[n], bc[n] * c[s]);
                p[n] = cc[n] * h[n];
            }
            #pragma unroll
            for (int st = 8; st >= 1; st >>= 1)
                #pragma unroll
                for (int n = 0; n < 8; n++)
                    if (n < st) p[n] += p[n + st];
            yo[(size_t)(t + s) * NE] = p[0];
        }
    }
}

// -------- launch --------
extern "C" void kernel_launch(void* const* d_in, const int* in_sizes, int n_in,
                              void* d_out, int out_size)
{
    const float* x      = (const float*)d_in[0];
    const float* gamma  = (const float*)d_in[1];
    const float* W_in   = (const float*)d_in[2];
    const float* b_in   = (const float*)d_in[3];
    const float* conv_w = (const float*)d_in[4];
    const float* A      = (const float*)d_in[5];
    const float* Bp     = (const float*)d_in[6];
    const float* C      = (const float*)d_in[7];
    const float* W_out  = (const float*)d_in[8];
    const float* b_out  = (const float*)d_in[9];
    float* out = (float*)d_out;

    void *p_xn, *p_xp, *p_y;
    cudaGetSymbolAddress(&p_xn, g_xn);
    cudaGetSymbolAddress(&p_xp, g_xp);
    cudaGetSymbolAddress(&p_y, g_y);

    precompute_kernel<<<(NST * NE + 255) / 256, 256>>>(A, Bp, C, conv_w);
    rmsnorm_kernel<<<NBL, 256>>>(x, gamma);

    dim3 g1(NE / 128, NBL / 128);
    gemm_tc_kernel<false><<<g1, 256>>>((const float*)p_xn, W_in, b_in, nullptr,
                                       (float*)p_xp, NBL, NE, DIMX);

    int nA = NB * NCHUNK * NE;
    ssm_passA_kernel<<<(nA + 255) / 256, 256>>>();
    int nB_ = NB * NST * NE;
    ssm_passB_kernel<<<(nB_ + 255) / 256, 256>>>();
    ssm_passC_kernel<<<(nA + 255) / 256, 256>>>();

    dim3 g2(DIMX / 128, NBL / 128);
    gemm_tc_kernel<true><<<g2, 256>>>((const float*)p_y, W_out, b_out, x,
                                      out, NBL, DIMX, NE);
}